// round 10
// baseline (speedup 1.0000x reference)
#include <cuda_runtime.h>
#include <cuda_bf16.h>

#define BB 4
#define PP 2048
#define NROWS (BB*PP)
#define NB 128          // persistent grid (<=148 SMs -> all co-resident)
#define NT 1024         // 32 warps -> 8 per SMSP

// ---------------- scratch (device globals; no allocation) ----------------
__device__ float g_encpsiT[BB*32*PP];     // psi output, feature-major [b][d][P]
__device__ float g_cumT   [BB*32*PP];     // cumsum, feature-major [b][d][P]
__device__ float g_encT   [BB*32*PP];     // phi output, feature-major [b][d][P]
__device__ float g_preattn[BB*4*PP];      // [b][h][P]
__device__ float g_agg2T  [BB*128*PP];    // out5, feature-major [b][h*32+d][P]

// ---------------- software grid barrier (monotonic generation) ----------------
__device__ unsigned g_cnt[8];
__device__ unsigned g_gen[8];

__device__ __forceinline__ void grid_bar(int i)
{
    __syncthreads();
    if (threadIdx.x == 0) {
        __threadfence();
        unsigned gen = *(volatile unsigned*)&g_gen[i];
        unsigned a = atomicAdd(&g_cnt[i], 1u);
        if (a == NB - 1u) {
            g_cnt[i] = 0u;
            __threadfence();
            atomicAdd(&g_gen[i], 1u);
        } else {
            while (*(volatile unsigned*)&g_gen[i] == gen) { }
            __threadfence();
        }
    }
    __syncthreads();
}

// ---------------- block scan helper (32 warps) ----------------
__device__ __forceinline__ float block_excl_from_tot(float tot, int tid, float* ws)
{
    __syncthreads();
    float x = tot;
#pragma unroll
    for (int o = 1; o < 32; o <<= 1) {
        float y = __shfl_up_sync(0xffffffffu, x, o);
        if ((tid & 31) >= o) x += y;
    }
    if ((tid & 31) == 31) ws[tid >> 5] = x;
    __syncthreads();
    float carry = 0.f;
    int w = tid >> 5;
    for (int i = 0; i < w; i++) carry += ws[i];
    return carry + x - tot;
}

// ---------------- fused persistent kernel ----------------
__global__ __launch_bounds__(NT, 1) void fused_all(
    const float* __restrict__ times, const float* __restrict__ values,
    const int* __restrict__ meas, const float* __restrict__ mask,
    const float* __restrict__ psi_w1, const float* __restrict__ psi_b1,
    const float* __restrict__ psi_w2, const float* __restrict__ psi_b2,
    const float* __restrict__ arho_w, const float* __restrict__ arho_b,
    const float* __restrict__ W_k,    const float* __restrict__ W_q,
    const float* __restrict__ pw1, const float* __restrict__ pb1,
    const float* __restrict__ pw2, const float* __restrict__ pb2,
    const float* __restrict__ rw1, const float* __restrict__ rb1,
    const float* __restrict__ rw2, const float* __restrict__ rb2,
    float* __restrict__ out)
{
    __shared__ float s_ew1[128*64];   // rho w1 (32 KB)
    __shared__ float s_ew2[64*64];    // rho w2 (16 KB)
    __shared__ float s_eb1[64], s_eb2[64];
    __shared__ float s_comb[64*32];   // raw combined features for this block's 64 rows (8 KB)
    __shared__ float S[9600];         // staged scratch union (38.4 KB)
    __shared__ float ws[5*32];        // scan exchange
    __shared__ float s_mrow[32];

    const int tid  = threadIdx.x;
    const int warp = tid >> 5, lane = tid & 31;

    // ============ Stage A: combined features + psi MLP -> encpsiT ============
    {
        float* sw1 = S;           // 992
        float* sw2 = S + 992;     // 1024
        float* sb1 = S + 2016;    // 32
        float* sb2 = S + 2048;    // 32
        float* xb  = S + 2080;    // 32*32
        float* hb  = S + 3104;    // 32*32
        float* sbuf= S + 4128;    // 32*33

        for (int i = tid; i < 992;  i += NT) sw1[i] = psi_w1[i];
        for (int i = tid; i < 1024; i += NT) sw2[i] = psi_w2[i];
        if (tid < 32) { sb1[tid] = psi_b1[tid]; sb2[tid] = psi_b2[tid]; }
        __syncthreads();

        for (int it = 0; it < 2; it++) {
            int vb  = blockIdx.x * 2 + it;
            int row = vb * 32 + warp;
            int b   = row >> 11;
            int p0  = (vb * 32) & 2047;
            float m = mask[row];

            float c;
            if (lane < 8) {
                const float pv[8] = {1.f,1.f,10.f,10.f,100.f,100.f,1000.f,1000.f};
                float r = times[row] / pv[lane];
                c = ((lane & 1) == 0) ? sinf(r) : cosf(r);
            } else if (lane == 8) {
                c = values[row];
            } else if (lane <= 30) {
                c = (meas[row] == lane - 8) ? 1.f : 0.f;
            } else c = 0.f;

            s_comb[(it*32 + warp)*32 + lane] = c;
            xb[warp*32 + lane] = c * m;
            __syncwarp();

            // layer1: 4 independent accumulator chains
            float a0 = sb1[lane], a1 = 0.f, a2 = 0.f, a3 = 0.f;
#pragma unroll
            for (int i = 0; i < 8;  i++) a0 = fmaf(xb[warp*32 + i], sw1[i*32 + lane], a0);
#pragma unroll
            for (int i = 8; i < 16; i++) a1 = fmaf(xb[warp*32 + i], sw1[i*32 + lane], a1);
#pragma unroll
            for (int i = 16; i < 24;i++) a2 = fmaf(xb[warp*32 + i], sw1[i*32 + lane], a2);
#pragma unroll
            for (int i = 24; i < 31;i++) a3 = fmaf(xb[warp*32 + i], sw1[i*32 + lane], a3);
            hb[warp*32 + lane] = fmaxf((a0 + a2) + (a1 + a3), 0.f) * m;
            __syncwarp();

            a0 = sb2[lane]; a1 = 0.f; a2 = 0.f; a3 = 0.f;
#pragma unroll
            for (int i = 0; i < 8;  i++) a0 = fmaf(hb[warp*32 + i], sw2[i*32 + lane], a0);
#pragma unroll
            for (int i = 8; i < 16; i++) a1 = fmaf(hb[warp*32 + i], sw2[i*32 + lane], a1);
#pragma unroll
            for (int i = 16; i < 24;i++) a2 = fmaf(hb[warp*32 + i], sw2[i*32 + lane], a2);
#pragma unroll
            for (int i = 24; i < 32;i++) a3 = fmaf(hb[warp*32 + i], sw2[i*32 + lane], a3);
            sbuf[warp*33 + lane] = fmaxf((a0 + a2) + (a1 + a3), 0.f) * m;
            __syncthreads();

            // transposed coalesced write: warp=feature d, lane=p within tile
            g_encpsiT[(b*32 + warp)*PP + p0 + lane] = sbuf[lane*33 + warp];
            __syncthreads();
        }
    }
    grid_bar(0);

    // ---- prefetch stage-C weights + rho weights into smem (overlaps stage B) ----
    {
        float* sar  = S;          // 1024
        float* sw1  = S + 1024;   // 992
        float* sw2  = S + 2016;   // 1024
        float* sWkq = S + 3040;   // 252
        float* sarb = S + 3292;   // 32
        float* sb1  = S + 3324;   // 32
        float* sb2  = S + 3356;   // 32
        for (int i = tid; i < 1024; i += NT) { sar[i] = arho_w[i]; sw2[i] = pw2[i]; }
        for (int i = tid; i < 992;  i += NT) sw1[i] = pw1[i];
        if (tid < 32) { sarb[tid] = arho_b[tid]; sb1[tid] = pb1[tid]; sb2[tid] = pb2[tid]; }
        for (int j = tid; j < 252; j += NT) {     // fold W_k @ W_q per head
            int h = j / 63, i = j % 63;
            float a = 0.f;
#pragma unroll
            for (int dd = 0; dd < 16; dd++)
                a = fmaf(W_k[i*64 + dd*4 + h], W_q[h*16 + dd], a);
            sWkq[h*63 + i] = a;
        }
        for (int i = tid; i < 128*64; i += NT) s_ew1[i] = rw1[i];
        for (int i = tid; i < 64*64;  i += NT) s_ew2[i] = rw2[i];
        if (tid < 64) { s_eb1[tid] = rb1[tid]; s_eb2[tid] = rb2[tid]; }
    }

    // ============ Stage B: cumsum along P per (b,d) ============
    {
        int id = blockIdx.x;              // b*32+d
        const float2* in2 = (const float2*)(g_encpsiT + id*PP);
        float2* out2 = (float2*)(g_cumT + id*PP);

        float2 a = in2[tid];
        float v0 = a.x, v1 = a.x + a.y;
        float excl = block_excl_from_tot(v1, tid, ws);
        out2[tid] = make_float2(v0 + excl, v1 + excl);
    }
    grid_bar(1);

    // ============ Stage C: arho + preattn + phi MLP -> encT ============
    {
        float* sar  = S;
        float* sw1  = S + 1024;
        float* sw2  = S + 2016;
        float* sWkq = S + 3040;
        float* sarb = S + 3292;
        float* sb1  = S + 3324;
        float* sb2  = S + 3356;
        float* c2   = S + 3392;   // 32*64 = 2048
        float* hb   = S + 5440;   // 32*32
        float* xb   = S + 6464;   // 32*32
        float* sc   = S + 7488;   // 32*33
        float* eb   = S + 8544;   // 32*33

        for (int it = 0; it < 2; it++) {
            int vb  = blockIdx.x * 2 + it;
            int row = vb * 32 + warp;
            int b   = row >> 11, p = row & 2047;
            int p0  = (vb * 32) & 2047;
            float m = mask[row];

            {   // cum tile: warp=feature d, lane=p; pre-apply 1/count and mask
                float mm = mask[b*PP + p0 + lane];
                sc[lane*33 + warp] = g_cumT[(b*32 + warp)*PP + p0 + lane]
                                     * (1.f/(float)(p0 + lane + 1)) * mm;
            }
            float c = s_comb[(it*32 + warp)*32 + lane];
            c2[warp*64 + lane] = c;
            xb[warp*32 + lane] = (lane < 31) ? c * m : 0.f;
            __syncthreads();   // sc ready

            // arho matmul: 4 accumulator chains
            float a0 = sarb[lane], a1 = 0.f, a2 = 0.f, a3 = 0.f;
#pragma unroll
            for (int i = 0; i < 8;  i++) a0 = fmaf(sc[warp*33 + i], sar[i*32 + lane], a0);
#pragma unroll
            for (int i = 8; i < 16; i++) a1 = fmaf(sc[warp*33 + i], sar[i*32 + lane], a1);
#pragma unroll
            for (int i = 16; i < 24;i++) a2 = fmaf(sc[warp*33 + i], sar[i*32 + lane], a2);
#pragma unroll
            for (int i = 24; i < 32;i++) a3 = fmaf(sc[warp*33 + i], sar[i*32 + lane], a3);
            c2[warp*64 + 31 + lane] = ((a0 + a2) + (a1 + a3)) * m;
            __syncwarp();

            // preattn: 8 lanes per head
            int h = lane >> 3, ls = lane & 7;
            float pa = 0.f;
            for (int i = ls; i < 63; i += 8) pa = fmaf(c2[warp*64 + i], sWkq[h*63 + i], pa);
            pa += __shfl_xor_sync(0xffffffffu, pa, 1);
            pa += __shfl_xor_sync(0xffffffffu, pa, 2);
            pa += __shfl_xor_sync(0xffffffffu, pa, 4);
            if (ls == 0) g_preattn[(b*4 + h)*PP + p] = pa * 0.25f * m * m;

            // phi MLP layer1
            a0 = sb1[lane]; a1 = 0.f; a2 = 0.f; a3 = 0.f;
#pragma unroll
            for (int i = 0; i < 8;  i++) a0 = fmaf(xb[warp*32 + i], sw1[i*32 + lane], a0);
#pragma unroll
            for (int i = 8; i < 16; i++) a1 = fmaf(xb[warp*32 + i], sw1[i*32 + lane], a1);
#pragma unroll
            for (int i = 16; i < 24;i++) a2 = fmaf(xb[warp*32 + i], sw1[i*32 + lane], a2);
#pragma unroll
            for (int i = 24; i < 31;i++) a3 = fmaf(xb[warp*32 + i], sw1[i*32 + lane], a3);
            hb[warp*32 + lane] = fmaxf((a0 + a2) + (a1 + a3), 0.f) * m;
            __syncwarp();

            a0 = sb2[lane]; a1 = 0.f; a2 = 0.f; a3 = 0.f;
#pragma unroll
            for (int i = 0; i < 8;  i++) a0 = fmaf(hb[warp*32 + i], sw2[i*32 + lane], a0);
#pragma unroll
            for (int i = 8; i < 16; i++) a1 = fmaf(hb[warp*32 + i], sw2[i*32 + lane], a1);
#pragma unroll
            for (int i = 16; i < 24;i++) a2 = fmaf(hb[warp*32 + i], sw2[i*32 + lane], a2);
#pragma unroll
            for (int i = 24; i < 32;i++) a3 = fmaf(hb[warp*32 + i], sw2[i*32 + lane], a3);
            eb[warp*33 + lane] = fmaxf((a0 + a2) + (a1 + a3), 0.f) * m;
            __syncthreads();

            g_encT[(b*32 + warp)*PP + p0 + lane] = eb[lane*33 + warp];
            __syncthreads();
        }
    }
    grid_bar(2);

    // ============ Stage D: batched softmax-denominator + 4 numerator scans ============
    // No max-subtraction: num/den ratio is shift-invariant; preattn O(1) (validated 3e-7).
    {
        int id = blockIdx.x;
        int bh = id >> 3, dg = id & 7;
        int b = bh >> 2, h = bh & 3;

        float2 A = ((const float2*)(g_preattn + bh*PP))[tid];
        float w0 = __expf(A.x), w1 = __expf(A.y);
        float den0 = w0, den1 = w0 + w1;

        float2 E[4];
#pragma unroll
        for (int j = 0; j < 4; j++)
            E[j] = ((const float2*)(g_encT + (b*32 + dg*4 + j)*PP))[tid];

        float n0[4], n1[4];
#pragma unroll
        for (int j = 0; j < 4; j++) { n0[j] = w0*E[j].x; n1[j] = n0[j] + w1*E[j].y; }

        // 5 interleaved warp scans (denominator + 4 numerators)
        float tot[5] = {den1, n1[0], n1[1], n1[2], n1[3]};
        float x[5] = {tot[0], tot[1], tot[2], tot[3], tot[4]};
#pragma unroll
        for (int o = 1; o < 32; o <<= 1) {
#pragma unroll
            for (int k = 0; k < 5; k++) {
                float y = __shfl_up_sync(0xffffffffu, x[k], o);
                if (lane >= o) x[k] += y;
            }
        }
        __syncthreads();              // protect ws reuse
        if (lane == 31) {
#pragma unroll
            for (int k = 0; k < 5; k++) ws[k*32 + warp] = x[k];
        }
        __syncthreads();
        float excl[5];
#pragma unroll
        for (int k = 0; k < 5; k++) {
            float pre = (lane < warp) ? ws[k*32 + lane] : 0.f;
#pragma unroll
            for (int o = 16; o > 0; o >>= 1) pre += __shfl_xor_sync(0xffffffffu, pre, o);
            excl[k] = pre + x[k] - tot[k];
        }

        float r0 = 1.0f / (den0 + excl[0]);
        float r1 = 1.0f / (den1 + excl[0]);

        float2 M = ((const float2*)(mask + b*PP))[tid];
#pragma unroll
        for (int j = 0; j < 4; j++) {
            float o0 = (n0[j] + excl[j+1]) * r0 * M.x;
            float o1 = (n1[j] + excl[j+1]) * r1 * M.y;
            ((float2*)(g_agg2T + (b*128 + h*32 + dg*4 + j)*PP))[tid] = make_float2(o0, o1);
        }
    }
    grid_bar(3);

    // ============ Stage E: rho MLP 128->64->64 ============
    {
        float* tile = S;          // 128*33 = 4224
        float* hbuf = S + 4224;   // 32*65 = 2080

        for (int it = 0; it < 2; it++) {
            int r0i = (blockIdx.x * 2 + it) * 32;
            int b = r0i >> 11, p0 = r0i & 2047;
            if (tid < 32) s_mrow[tid] = mask[r0i + tid];
            __syncthreads();

            for (int idx = tid; idx < 128*32; idx += NT) {
                int f = idx >> 5, pi = idx & 31;
                tile[f*33 + pi] = g_agg2T[(b*128 + f)*PP + p0 + pi] * s_mrow[pi];
            }
            __syncthreads();

            // 1 row per warp (pi = warp); even/odd f split for ILP
            float m = s_mrow[warp];
            float a0e = s_eb1[lane], a0o = 0.f, a1e = s_eb1[lane+32], a1o = 0.f;
#pragma unroll 16
            for (int f = 0; f < 128; f += 2) {
                float xe = tile[f*33 + warp];
                float xo = tile[(f+1)*33 + warp];
                a0e = fmaf(xe, s_ew1[f*64 + lane],          a0e);
                a1e = fmaf(xe, s_ew1[f*64 + lane + 32],     a1e);
                a0o = fmaf(xo, s_ew1[(f+1)*64 + lane],      a0o);
                a1o = fmaf(xo, s_ew1[(f+1)*64 + lane + 32], a1o);
            }
            hbuf[warp*65 + lane]      = fmaxf(a0e + a0o, 0.f) * m;
            hbuf[warp*65 + lane + 32] = fmaxf(a1e + a1o, 0.f) * m;
            __syncwarp();

            a0e = s_eb2[lane]; a0o = 0.f; a1e = s_eb2[lane+32]; a1o = 0.f;
#pragma unroll 16
            for (int i = 0; i < 64; i += 2) {
                float he = hbuf[warp*65 + i];
                float ho = hbuf[warp*65 + i + 1];
                a0e = fmaf(he, s_ew2[i*64 + lane],          a0e);
                a1e = fmaf(he, s_ew2[i*64 + lane + 32],     a1e);
                a0o = fmaf(ho, s_ew2[(i+1)*64 + lane],      a0o);
                a1o = fmaf(ho, s_ew2[(i+1)*64 + lane + 32], a1o);
            }
            int row = r0i + warp;
            out[row*64 + lane]      = fmaxf(a0e + a0o, 0.f) * m;
            out[row*64 + lane + 32] = fmaxf(a1e + a1o, 0.f) * m;
            __syncthreads();
        }
    }
}

// ---------------- launch ----------------
extern "C" void kernel_launch(void* const* d_in, const int* in_sizes, int n_in,
                              void* d_out, int out_size)
{
    const float* times  = (const float*)d_in[0];
    const float* values = (const float*)d_in[1];
    const int*   meas   = (const int*)  d_in[2];
    const float* mask   = (const float*)d_in[3];
    const float* psi_w1 = (const float*)d_in[4];
    const float* psi_b1 = (const float*)d_in[5];
    const float* psi_w2 = (const float*)d_in[6];
    const float* psi_b2 = (const float*)d_in[7];
    const float* arho_w = (const float*)d_in[8];
    const float* arho_b = (const float*)d_in[9];
    const float* W_k    = (const float*)d_in[10];
    const float* W_q    = (const float*)d_in[11];
    const float* phi_w1 = (const float*)d_in[12];
    const float* phi_b1 = (const float*)d_in[13];
    const float* phi_w2 = (const float*)d_in[14];
    const float* phi_b2 = (const float*)d_in[15];
    const float* rho_w1 = (const float*)d_in[16];
    const float* rho_b1 = (const float*)d_in[17];
    const float* rho_w2 = (const float*)d_in[18];
    const float* rho_b2 = (const float*)d_in[19];
    float* out = (float*)d_out;

    fused_all<<<NB, NT>>>(times, values, meas, mask,
                          psi_w1, psi_b1, psi_w2, psi_b2,
                          arho_w, arho_b, W_k, W_q,
                          phi_w1, phi_b1, phi_w2, phi_b2,
                          rho_w1, rho_b1, rho_w2, rho_b2, out);
}

// round 15
// speedup vs baseline: 1.2261x; 1.2261x over previous
#include <cuda_runtime.h>
#include <cuda_bf16.h>

#define BB 4
#define PP 2048
#define NROWS (BB*PP)
#define NB 128          // persistent grid (<=148 SMs -> all co-resident)
#define NT 512          // 16 warps

// ---------------- scratch (device globals; no allocation) ----------------
__device__ float g_encpsiT[BB*32*PP];     // psi output, feature-major [b][d][P]
__device__ float g_cumT   [BB*32*PP];     // cumsum, feature-major [b][d][P]
__device__ float g_encT   [BB*32*PP];     // phi output, feature-major [b][d][P]
__device__ float g_preattn[BB*4*PP];      // [b][h][P]
__device__ float g_agg2T  [BB*128*PP];    // out5, feature-major [b][h*32+d][P]

// ---------------- software grid barrier (monotonic generation) ----------------
__device__ unsigned g_cnt[8];
__device__ unsigned g_gen[8];

__device__ __forceinline__ void grid_bar(int i)
{
    __syncthreads();
    if (threadIdx.x == 0) {
        __threadfence();
        unsigned gen = *(volatile unsigned*)&g_gen[i];
        unsigned a = atomicAdd(&g_cnt[i], 1u);
        if (a == NB - 1u) {
            g_cnt[i] = 0u;
            __threadfence();
            atomicAdd(&g_gen[i], 1u);
        } else {
            while (*(volatile unsigned*)&g_gen[i] == gen) { }
            __threadfence();
        }
    }
    __syncthreads();
}

// ---------------- block scan helper (16 warps) ----------------
__device__ __forceinline__ float block_excl_from_tot(float tot, int tid, float* ws)
{
    __syncthreads();
    float x = tot;
#pragma unroll
    for (int o = 1; o < 32; o <<= 1) {
        float y = __shfl_up_sync(0xffffffffu, x, o);
        if ((tid & 31) >= o) x += y;
    }
    if ((tid & 31) == 31) ws[tid >> 5] = x;
    __syncthreads();
    float carry = 0.f;
    int w = tid >> 5;
    for (int i = 0; i < w; i++) carry += ws[i];
    return carry + x - tot;
}

// ---------------- fused persistent kernel ----------------
__global__ __launch_bounds__(NT, 1) void fused_all(
    const float* __restrict__ times, const float* __restrict__ values,
    const int* __restrict__ meas, const float* __restrict__ mask,
    const float* __restrict__ psi_w1, const float* __restrict__ psi_b1,
    const float* __restrict__ psi_w2, const float* __restrict__ psi_b2,
    const float* __restrict__ arho_w, const float* __restrict__ arho_b,
    const float* __restrict__ W_k,    const float* __restrict__ W_q,
    const float* __restrict__ pw1, const float* __restrict__ pb1,
    const float* __restrict__ pw2, const float* __restrict__ pb2,
    const float* __restrict__ rw1, const float* __restrict__ rb1,
    const float* __restrict__ rw2, const float* __restrict__ rb2,
    float* __restrict__ out)
{
    __shared__ float s_ew1[128*64];   // rho w1 (32 KB)
    __shared__ float s_ew2[64*64];    // rho w2 (16 KB)
    __shared__ float s_eb1[64], s_eb2[64];
    __shared__ float xb[64*33];       // masked combined features, 64 rows (8.4 KB), lives A->C
    __shared__ float S[14336];        // staged scratch union (57.3 KB)
    __shared__ float ws[5*16];        // scan exchange
    __shared__ float mrow[64];

    const int tid  = threadIdx.x;
    const int warp = tid >> 5, lane = tid & 31;
    const int base = blockIdx.x * 64;        // this block's 64 rows
    const int b    = base >> 11;
    const int p0   = base & 2047;
    const int w4   = warp * 4;               // first of this warp's 4 rows

    if (tid < 64) mrow[tid] = mask[base + tid];

    // ============ Stage A: combined features + psi MLP -> encpsiT ============
    {
        float* sw1 = S;           // 992
        float* sw2 = S + 992;     // 1024
        float* sb1 = S + 2016;    // 32
        float* sb2 = S + 2048;    // 32
        float* hb  = S + 2080;    // 64*33
        float* eb  = S + 4192;    // 64*33

        for (int i = tid; i < 992;  i += NT) sw1[i] = psi_w1[i];
        for (int i = tid; i < 1024; i += NT) sw2[i] = psi_w2[i];
        if (tid < 32) { sb1[tid] = psi_b1[tid]; sb2[tid] = psi_b2[tid]; }

        // feature gen: 4 passes, warp = row within pass, lane = feature
        for (int it = 0; it < 4; it++) {
            int rl  = it*16 + warp;
            int row = base + rl;
            float c;
            if (lane < 8) {
                const float pv[8] = {1.f,1.f,10.f,10.f,100.f,100.f,1000.f,1000.f};
                float r = times[row] / pv[lane];
                c = ((lane & 1) == 0) ? sinf(r) : cosf(r);
            } else if (lane == 8) {
                c = values[row];
            } else if (lane <= 30) {
                c = (meas[row] == lane - 8) ? 1.f : 0.f;
            } else c = 0.f;
            xb[rl*33 + lane] = c * mask[row];   // masked features (mask is 0/1)
        }
        __syncthreads();

        // psi layer1, R=4 rows per warp (weight loaded once per 4 FMAs)
        float acc[4];
#pragma unroll
        for (int r = 0; r < 4; r++) acc[r] = sb1[lane];
        for (int i = 0; i < 31; i++) {
            float wv = sw1[i*32 + lane];
#pragma unroll
            for (int r = 0; r < 4; r++) acc[r] = fmaf(xb[(w4+r)*33 + i], wv, acc[r]);
        }
#pragma unroll
        for (int r = 0; r < 4; r++)
            hb[(w4+r)*33 + lane] = fmaxf(acc[r], 0.f) * mrow[w4+r];
        __syncthreads();

        // psi layer2
#pragma unroll
        for (int r = 0; r < 4; r++) acc[r] = sb2[lane];
        for (int i = 0; i < 32; i++) {
            float wv = sw2[i*32 + lane];
#pragma unroll
            for (int r = 0; r < 4; r++) acc[r] = fmaf(hb[(w4+r)*33 + i], wv, acc[r]);
        }
#pragma unroll
        for (int r = 0; r < 4; r++)
            eb[(w4+r)*33 + lane] = fmaxf(acc[r], 0.f) * mrow[w4+r];
        __syncthreads();

        // transposed coalesced write: 64 consecutive p per feature d (256B)
        for (int idx = tid; idx < 2048; idx += NT) {
            int d = idx >> 6, pp = idx & 63;
            g_encpsiT[(b*32 + d)*PP + p0 + pp] = eb[pp*33 + d];
        }
    }
    grid_bar(0);

    // ---- prefetch stage-C weights + rho weights (overlaps stage B) ----
    {
        float* sar  = S;          // 1024
        float* sw1  = S + 1024;   // 992
        float* sw2  = S + 2016;   // 1024
        float* sWkq = S + 3040;   // 252
        float* sarb = S + 3292;   // 32
        float* sb1  = S + 3324;   // 32
        float* sb2  = S + 3356;   // 32
        for (int i = tid; i < 1024; i += NT) { sar[i] = arho_w[i]; sw2[i] = pw2[i]; }
        for (int i = tid; i < 992;  i += NT) sw1[i] = pw1[i];
        if (tid < 32) { sarb[tid] = arho_b[tid]; sb1[tid] = pb1[tid]; sb2[tid] = pb2[tid]; }
        for (int j = tid; j < 252; j += NT) {     // fold W_k @ W_q per head
            int h = j / 63, i = j % 63;
            float a = 0.f;
#pragma unroll
            for (int dd = 0; dd < 16; dd++)
                a = fmaf(W_k[i*64 + dd*4 + h], W_q[h*16 + dd], a);
            sWkq[h*63 + i] = a;
        }
        for (int i = tid; i < 128*64; i += NT) s_ew1[i] = rw1[i];
        for (int i = tid; i < 64*64;  i += NT) s_ew2[i] = rw2[i];
        if (tid < 64) { s_eb1[tid] = rb1[tid]; s_eb2[tid] = rb2[tid]; }
    }

    // ============ Stage B: cumsum along P per (b,d) ============
    {
        int id = blockIdx.x;              // b*32+d
        const float4* in4 = (const float4*)(g_encpsiT + id*PP);
        float4* out4 = (float4*)(g_cumT + id*PP);

        float4 a = in4[tid];
        float v[4] = {a.x, a.y, a.z, a.w};
#pragma unroll
        for (int i = 1; i < 4; i++) v[i] += v[i-1];
        float excl = block_excl_from_tot(v[3], tid, ws);
        out4[tid] = make_float4(v[0]+excl, v[1]+excl, v[2]+excl, v[3]+excl);
    }
    grid_bar(1);

    // ============ Stage C: arho + preattn + phi MLP -> encT ============
    {
        float* sar  = S;
        float* sw1  = S + 1024;
        float* sw2  = S + 2016;
        float* sWkq = S + 3040;
        float* sarb = S + 3292;
        float* sb1  = S + 3324;
        float* sb2  = S + 3356;
        float* c2   = S + 3392;   // 64*66 = 4224
        float* hb   = S + 7616;   // 64*33
        float* sc   = S + 9728;   // 64*33
        float* eb   = S + 11840;  // 64*33

        // cum tile (coalesced 256B reads), pre-apply 1/count and mask
        for (int idx = tid; idx < 2048; idx += NT) {
            int d = idx >> 6, pp = idx & 63;
            sc[pp*33 + d] = g_cumT[(b*32 + d)*PP + p0 + pp]
                            * (1.f/(float)(p0 + pp + 1)) * mrow[pp];
        }
        // c2[row][0..30] = masked combined
        for (int idx = tid; idx < 2048; idx += NT) {
            int r = idx >> 5, l = idx & 31;
            if (l < 31) c2[r*66 + l] = xb[r*33 + l];
        }
        __syncthreads();

        // arho matmul, R=4
        float acc[4];
#pragma unroll
        for (int r = 0; r < 4; r++) acc[r] = sarb[lane];
        for (int i = 0; i < 32; i++) {
            float wv = sar[i*32 + lane];
#pragma unroll
            for (int r = 0; r < 4; r++) acc[r] = fmaf(sc[(w4+r)*33 + i], wv, acc[r]);
        }
#pragma unroll
        for (int r = 0; r < 4; r++)
            c2[(w4+r)*66 + 31 + lane] = acc[r] * mrow[w4+r];
        __syncthreads();

        // preattn: 8 lanes per head, 4 rows per warp
        {
            int h = lane >> 3, ls = lane & 7;
#pragma unroll
            for (int r = 0; r < 4; r++) {
                int rl = w4 + r;
                float pa = 0.f;
                for (int i = ls; i < 63; i += 8)
                    pa = fmaf(c2[rl*66 + i], sWkq[h*63 + i], pa);
                pa += __shfl_xor_sync(0xffffffffu, pa, 1);
                pa += __shfl_xor_sync(0xffffffffu, pa, 2);
                pa += __shfl_xor_sync(0xffffffffu, pa, 4);
                if (ls == 0)
                    g_preattn[(b*4 + h)*PP + p0 + rl] = pa * 0.25f * mrow[rl];
            }
        }

        // phi layer1, R=4
#pragma unroll
        for (int r = 0; r < 4; r++) acc[r] = sb1[lane];
        for (int i = 0; i < 31; i++) {
            float wv = sw1[i*32 + lane];
#pragma unroll
            for (int r = 0; r < 4; r++) acc[r] = fmaf(xb[(w4+r)*33 + i], wv, acc[r]);
        }
#pragma unroll
        for (int r = 0; r < 4; r++)
            hb[(w4+r)*33 + lane] = fmaxf(acc[r], 0.f) * mrow[w4+r];
        __syncthreads();

        // phi layer2
#pragma unroll
        for (int r = 0; r < 4; r++) acc[r] = sb2[lane];
        for (int i = 0; i < 32; i++) {
            float wv = sw2[i*32 + lane];
#pragma unroll
            for (int r = 0; r < 4; r++) acc[r] = fmaf(hb[(w4+r)*33 + i], wv, acc[r]);
        }
#pragma unroll
        for (int r = 0; r < 4; r++)
            eb[(w4+r)*33 + lane] = fmaxf(acc[r], 0.f) * mrow[w4+r];
        __syncthreads();

        for (int idx = tid; idx < 2048; idx += NT) {
            int d = idx >> 6, pp = idx & 63;
            g_encT[(b*32 + d)*PP + p0 + pp] = eb[pp*33 + d];
        }
    }
    grid_bar(2);

    // ============ Stage D: batched softmax-denominator + 4 numerator scans ============
    // No max-subtraction: num/den ratio is shift-invariant; preattn O(1) (validated 3e-7).
    {
        int id = blockIdx.x;
        int bh = id >> 3, dg = id & 7;
        int bD = bh >> 2, h = bh & 3;

        float4 A = ((const float4*)(g_preattn + bh*PP))[tid];
        float w0 = __expf(A.x), w1 = __expf(A.y), w2 = __expf(A.z), w3 = __expf(A.w);
        float d0 = w0, d1 = d0 + w1, d2 = d1 + w2, d3 = d2 + w3;

        float4 E[4];
#pragma unroll
        for (int j = 0; j < 4; j++)
            E[j] = ((const float4*)(g_encT + (bD*32 + dg*4 + j)*PP))[tid];

        float n0[4], n1[4], n2[4], n3[4];
#pragma unroll
        for (int j = 0; j < 4; j++) {
            n0[j] = w0*E[j].x;
            n1[j] = n0[j] + w1*E[j].y;
            n2[j] = n1[j] + w2*E[j].z;
            n3[j] = n2[j] + w3*E[j].w;
        }

        // 5 interleaved warp scans (denominator + 4 numerators)
        float tot[5] = {d3, n3[0], n3[1], n3[2], n3[3]};
        float x[5] = {tot[0], tot[1], tot[2], tot[3], tot[4]};
#pragma unroll
        for (int o = 1; o < 32; o <<= 1) {
#pragma unroll
            for (int k = 0; k < 5; k++) {
                float y = __shfl_up_sync(0xffffffffu, x[k], o);
                if (lane >= o) x[k] += y;
            }
        }
        __syncthreads();              // protect ws reuse
        if (lane == 31) {
#pragma unroll
            for (int k = 0; k < 5; k++) ws[k*16 + warp] = x[k];
        }
        __syncthreads();
        float excl[5];
#pragma unroll
        for (int k = 0; k < 5; k++) {
            float pre = (lane < warp) ? ws[k*16 + lane] : 0.f;
#pragma unroll
            for (int o = 16; o > 0; o >>= 1) pre += __shfl_xor_sync(0xffffffffu, pre, o);
            excl[k] = pre + x[k] - tot[k];
        }

        float r0 = 1.0f / (d0 + excl[0]);
        float r1 = 1.0f / (d1 + excl[0]);
        float r2 = 1.0f / (d2 + excl[0]);
        float r3 = 1.0f / (d3 + excl[0]);

        float4 M = ((const float4*)(mask + bD*PP))[tid];
#pragma unroll
        for (int j = 0; j < 4; j++) {
            float4 o4;
            o4.x = (n0[j] + excl[j+1]) * r0 * M.x;
            o4.y = (n1[j] + excl[j+1]) * r1 * M.y;
            o4.z = (n2[j] + excl[j+1]) * r2 * M.z;
            o4.w = (n3[j] + excl[j+1]) * r3 * M.w;
            ((float4*)(g_agg2T + (bD*128 + h*32 + dg*4 + j)*PP))[tid] = o4;
        }
    }
    grid_bar(3);

    // ============ Stage E: rho MLP 128->64->64, 64 rows, R=4 per warp ============
    {
        float* tile = S;          // 128*65 = 8320
        float* hbuf = S + 8320;   // 64*65 = 4160

        // coalesced tile load: 64 consecutive p per feature f (256B)
        for (int idx = tid; idx < 128*64; idx += NT) {
            int f = idx >> 6, pp = idx & 63;
            tile[f*65 + pp] = g_agg2T[(b*128 + f)*PP + p0 + pp] * mrow[pp];
        }
        __syncthreads();

        // layer1: per f: 2 weight LDS + 4 broadcasts -> 8 FMA
        float a0[4], a1[4];
#pragma unroll
        for (int r = 0; r < 4; r++) { a0[r] = s_eb1[lane]; a1[r] = s_eb1[lane+32]; }
#pragma unroll 8
        for (int f = 0; f < 128; f++) {
            float wv0 = s_ew1[f*64 + lane];
            float wv1 = s_ew1[f*64 + lane + 32];
#pragma unroll
            for (int r = 0; r < 4; r++) {
                float xv = tile[f*65 + (w4 + r)];
                a0[r] = fmaf(xv, wv0, a0[r]);
                a1[r] = fmaf(xv, wv1, a1[r]);
            }
        }
#pragma unroll
        for (int r = 0; r < 4; r++) {
            int pi = w4 + r;
            float m = mrow[pi];
            hbuf[pi*65 + lane]      = fmaxf(a0[r], 0.f) * m;
            hbuf[pi*65 + lane + 32] = fmaxf(a1[r], 0.f) * m;
        }
        __syncthreads();

        // layer2
#pragma unroll
        for (int r = 0; r < 4; r++) { a0[r] = s_eb2[lane]; a1[r] = s_eb2[lane+32]; }
#pragma unroll 8
        for (int i = 0; i < 64; i++) {
            float wv0 = s_ew2[i*64 + lane];
            float wv1 = s_ew2[i*64 + lane + 32];
#pragma unroll
            for (int r = 0; r < 4; r++) {
                float hv = hbuf[(w4 + r)*65 + i];
                a0[r] = fmaf(hv, wv0, a0[r]);
                a1[r] = fmaf(hv, wv1, a1[r]);
            }
        }
#pragma unroll
        for (int r = 0; r < 4; r++) {
            int pi = w4 + r;
            float m = mrow[pi];
            int row = base + pi;
            out[row*64 + lane]      = fmaxf(a0[r], 0.f) * m;
            out[row*64 + lane + 32] = fmaxf(a1[r], 0.f) * m;
        }
    }
}

// ---------------- launch ----------------
extern "C" void kernel_launch(void* const* d_in, const int* in_sizes, int n_in,
                              void* d_out, int out_size)
{
    const float* times  = (const float*)d_in[0];
    const float* values = (const float*)d_in[1];
    const int*   meas   = (const int*)  d_in[2];
    const float* mask   = (const float*)d_in[3];
    const float* psi_w1 = (const float*)d_in[4];
    const float* psi_b1 = (const float*)d_in[5];
    const float* psi_w2 = (const float*)d_in[6];
    const float* psi_b2 = (const float*)d_in[7];
    const float* arho_w = (const float*)d_in[8];
    const float* arho_b = (const float*)d_in[9];
    const float* W_k    = (const float*)d_in[10];
    const float* W_q    = (const float*)d_in[11];
    const float* phi_w1 = (const float*)d_in[12];
    const float* phi_b1 = (const float*)d_in[13];
    const float* phi_w2 = (const float*)d_in[14];
    const float* phi_b2 = (const float*)d_in[15];
    const float* rho_w1 = (const float*)d_in[16];
    const float* rho_b1 = (const float*)d_in[17];
    const float* rho_w2 = (const float*)d_in[18];
    const float* rho_b2 = (const float*)d_in[19];
    float* out = (float*)d_out;

    fused_all<<<NB, NT>>>(times, values, meas, mask,
                          psi_w1, psi_b1, psi_w2, psi_b2,
                          arho_w, arho_b, W_k, W_q,
                          phi_w1, phi_b1, phi_w2, phi_b2,
                          rho_w1, rho_b1, rho_w2, rho_b2, out);
}